// round 1
// baseline (speedup 1.0000x reference)
#include <cuda_runtime.h>

// ---------------------------------------------------------------------------
// SpatialLocalAwareAttention
// B=2, T=4, H=W=32, D=256, heads=8, dh=32, local 3x3
// Inputs (metadata order): x, gamma, beta, Wq, Wk, Wv, Wkl, Wvl, Wo, q_bias
// Output: (B, D, T, H, W) float32
// ---------------------------------------------------------------------------

#define D_MODEL 256
#define N_HEADS 8
#define DHEAD   32
#define BTDIM   8        // B*T
#define NTOK    1024     // H*W
#define NROWS   (BTDIM * NTOK)   // 8192
#define IMG     32

__device__ float g_xn [NROWS * D_MODEL];
__device__ float g_q  [NROWS * D_MODEL];
__device__ float g_k  [NROWS * D_MODEL];
__device__ float g_v  [NROWS * D_MODEL];
__device__ float g_kl [NROWS * D_MODEL];
__device__ float g_vl [NROWS * D_MODEL];
__device__ float g_ctx[NROWS * D_MODEL];

// ---------------------------------------------------------------------------
// Kernel 1: layernorm + (B,D,T,H,W) -> (BT*N, D) gather
// one block per row (bt,n), 256 threads (one per channel d)
// ---------------------------------------------------------------------------
__global__ __launch_bounds__(256) void ln_kernel(const float* __restrict__ x,
                                                 const float* __restrict__ gamma,
                                                 const float* __restrict__ beta)
{
    int row = blockIdx.x;            // bt*1024 + n
    int d   = threadIdx.x;           // 0..255
    int bt  = row >> 10;
    int n   = row & 1023;
    int b   = bt >> 2;
    int t   = bt & 3;

    float v = x[((size_t)(b * D_MODEL + d) * 4 + t) * 1024 + n];

    // block reduction of sum and sum of squares
    float s  = v;
    float s2 = v * v;
    #pragma unroll
    for (int off = 16; off > 0; off >>= 1) {
        s  += __shfl_down_sync(0xffffffffu, s,  off);
        s2 += __shfl_down_sync(0xffffffffu, s2, off);
    }
    __shared__ float ws[8], ws2[8];
    __shared__ float mu_s, rstd_s;
    int lane = d & 31, wid = d >> 5;
    if (lane == 0) { ws[wid] = s; ws2[wid] = s2; }
    __syncthreads();
    if (d == 0) {
        float a = 0.f, b2 = 0.f;
        #pragma unroll
        for (int w = 0; w < 8; w++) { a += ws[w]; b2 += ws2[w]; }
        float mu  = a * (1.0f / 256.0f);
        float var = b2 * (1.0f / 256.0f) - mu * mu;
        mu_s   = mu;
        rstd_s = rsqrtf(var + 1e-6f);
    }
    __syncthreads();
    g_xn[(size_t)row * 256 + d] = (v - mu_s) * rstd_s * gamma[d] + beta[d];
}

// ---------------------------------------------------------------------------
// Kernel 2: 5 fused projections: out = xn @ W^T  (M=8192, N=256, K=256)
// classic 128x128 tile, BK=8, 8x8 per thread, 256 threads.
// blockIdx.z selects {Wq,Wk,Wv,Wkl,Wvl}; epilogue writes (BT,h,N,dh) layout,
// adds q_bias for z==0.
// ---------------------------------------------------------------------------
__global__ __launch_bounds__(256) void proj_kernel(const float* __restrict__ Wq,
                                                   const float* __restrict__ Wk,
                                                   const float* __restrict__ Wv,
                                                   const float* __restrict__ Wkl,
                                                   const float* __restrict__ Wvl,
                                                   const float* __restrict__ qb)
{
    __shared__ float As[8][128];
    __shared__ float Bs[8][128];

    const int tid = threadIdx.x;
    const int m0  = blockIdx.y * 128;
    const int c0  = blockIdx.x * 128;

    const float* Wm;
    float* dst;
    switch (blockIdx.z) {
        case 0:  Wm = Wq;  dst = g_q;  break;
        case 1:  Wm = Wk;  dst = g_k;  break;
        case 2:  Wm = Wv;  dst = g_v;  break;
        case 3:  Wm = Wkl; dst = g_kl; break;
        default: Wm = Wvl; dst = g_vl; break;
    }

    const int arow = tid >> 1;
    const int acol = (tid & 1) * 4;
    const int tx   = tid & 15;
    const int ty   = tid >> 4;

    float acc[8][8];
    #pragma unroll
    for (int i = 0; i < 8; i++)
        #pragma unroll
        for (int j = 0; j < 8; j++) acc[i][j] = 0.f;

    for (int k0 = 0; k0 < 256; k0 += 8) {
        float4 av = *(const float4*)(g_xn + (size_t)(m0 + arow) * 256 + k0 + acol);
        float4 bv = *(const float4*)(Wm   + (size_t)(c0 + arow) * 256 + k0 + acol);
        As[acol + 0][arow] = av.x; As[acol + 1][arow] = av.y;
        As[acol + 2][arow] = av.z; As[acol + 3][arow] = av.w;
        Bs[acol + 0][arow] = bv.x; Bs[acol + 1][arow] = bv.y;
        Bs[acol + 2][arow] = bv.z; Bs[acol + 3][arow] = bv.w;
        __syncthreads();
        #pragma unroll
        for (int kk = 0; kk < 8; kk++) {
            float a[8], b[8];
            *(float4*)(a)     = *(const float4*)(&As[kk][ty * 8]);
            *(float4*)(a + 4) = *(const float4*)(&As[kk][ty * 8 + 4]);
            *(float4*)(b)     = *(const float4*)(&Bs[kk][tx * 8]);
            *(float4*)(b + 4) = *(const float4*)(&Bs[kk][tx * 8 + 4]);
            #pragma unroll
            for (int i = 0; i < 8; i++)
                #pragma unroll
                for (int j = 0; j < 8; j++)
                    acc[i][j] += a[i] * b[j];
        }
        __syncthreads();
    }

    // epilogue
    const bool addb = (blockIdx.z == 0);
    const int  c    = c0 + tx * 8;       // multiple of 8; same head for all 8 cols
    float bb[8];
    #pragma unroll
    for (int j = 0; j < 8; j++) bb[j] = addb ? qb[c + j] : 0.f;

    const int head = c >> 5;
    const int dh0  = c & 31;
    #pragma unroll
    for (int i = 0; i < 8; i++) {
        int m   = m0 + ty * 8 + i;
        int bt_ = m >> 10;
        int nn  = m & 1023;
        float* p = dst + (size_t)bt_ * (N_HEADS * NTOK * DHEAD)
                       + (size_t)head * (NTOK * DHEAD)
                       + (size_t)nn * DHEAD + dh0;
        float4 o0 = make_float4(acc[i][0] + bb[0], acc[i][1] + bb[1],
                                acc[i][2] + bb[2], acc[i][3] + bb[3]);
        float4 o1 = make_float4(acc[i][4] + bb[4], acc[i][5] + bb[5],
                                acc[i][6] + bb[6], acc[i][7] + bb[7]);
        *(float4*)(p)     = o0;
        *(float4*)(p + 4) = o1;
    }
}

// ---------------------------------------------------------------------------
// Kernel 3: attention with fused global (1024 keys) + local (3x3) softmax.
// block = (bt, h, 128-query tile), 128 threads, one query per thread.
// Online softmax over 16 key tiles of 64; per-tile scores staged in smem.
// ---------------------------------------------------------------------------
__global__ __launch_bounds__(128) void attn_kernel()
{
    __shared__ float ks [64 * 32];     // 8 KB
    __shared__ float vs [64 * 32];     // 8 KB
    __shared__ float ssc[64 * 128];    // 32 KB  (total 48 KB)

    const int tid = threadIdx.x;       // 0..127
    const int n   = blockIdx.x * 128 + tid;
    const int h   = blockIdx.y;
    const int bt  = blockIdx.z;
    const int bh  = bt * N_HEADS + h;
    const float factor = 0.17677669529663687f;   // 32^-0.5

    const float* qrow = g_q + ((size_t)bh * NTOK + n) * DHEAD;
    float4 qv[8];
    #pragma unroll
    for (int i = 0; i < 8; i++) qv[i] = ((const float4*)qrow)[i];

    float4 accv[8];
    #pragma unroll
    for (int i = 0; i < 8; i++) accv[i] = make_float4(0.f, 0.f, 0.f, 0.f);
    float m = -1e30f, l = 0.f;

    const float* kbase = g_k + (size_t)bh * NTOK * DHEAD;
    const float* vbase = g_v + (size_t)bh * NTOK * DHEAD;

    for (int t0 = 0; t0 < NTOK; t0 += 64) {
        __syncthreads();
        {
            const float4* kt = (const float4*)(kbase + (size_t)t0 * DHEAD);
            const float4* vt = (const float4*)(vbase + (size_t)t0 * DHEAD);
            #pragma unroll
            for (int i = tid; i < 512; i += 128) {
                ((float4*)ks)[i] = kt[i];
                ((float4*)vs)[i] = vt[i];
            }
        }
        __syncthreads();

        // pass 1: scores into smem, tile max
        float tmax = -1e30f;
        for (int g = 0; g < 64; g++) {
            const float4* kk4 = (const float4*)(ks + g * 32);
            float s = 0.f;
            #pragma unroll
            for (int d = 0; d < 8; d++) {
                float4 kk = kk4[d];
                s += qv[d].x * kk.x + qv[d].y * kk.y +
                     qv[d].z * kk.z + qv[d].w * kk.w;
            }
            s *= factor;
            ssc[g * 128 + tid] = s;
            tmax = fmaxf(tmax, s);
        }

        float mnew  = fmaxf(m, tmax);
        float scale = __expf(m - mnew);
        l *= scale;
        #pragma unroll
        for (int d = 0; d < 8; d++) {
            accv[d].x *= scale; accv[d].y *= scale;
            accv[d].z *= scale; accv[d].w *= scale;
        }
        m = mnew;

        // pass 2: exp + weighted accumulate
        for (int g = 0; g < 64; g++) {
            float p = __expf(ssc[g * 128 + tid] - m);
            l += p;
            const float4* vv4 = (const float4*)(vs + g * 32);
            #pragma unroll
            for (int d = 0; d < 8; d++) {
                float4 vv = vv4[d];
                accv[d].x += p * vv.x; accv[d].y += p * vv.y;
                accv[d].z += p * vv.z; accv[d].w += p * vv.w;
            }
        }
    }

    // local 3x3 neighborhood (kl/vl), invalid neighbors skipped (== -inf mask)
    {
        const float* klb = g_kl + (size_t)bh * NTOK * DHEAD;
        const float* vlb = g_vl + (size_t)bh * NTOK * DHEAD;
        const int qi = n >> 5, qj = n & 31;

        float sl[9];
        int   gl[9];
        int   cnt  = 0;
        float lmax = -1e30f;
        #pragma unroll
        for (int oi = -1; oi <= 1; oi++) {
            #pragma unroll
            for (int oj = -1; oj <= 1; oj++) {
                int ni = qi + oi, nj = qj + oj;
                if (ni < 0 || ni >= IMG || nj < 0 || nj >= IMG) continue;
                int g = ni * IMG + nj;
                const float4* kk4 = (const float4*)(klb + (size_t)g * DHEAD);
                float s = 0.f;
                #pragma unroll
                for (int d = 0; d < 8; d++) {
                    float4 kk = kk4[d];
                    s += qv[d].x * kk.x + qv[d].y * kk.y +
                         qv[d].z * kk.z + qv[d].w * kk.w;
                }
                s *= factor;
                sl[cnt] = s;
                gl[cnt] = g;
                cnt++;
                lmax = fmaxf(lmax, s);
            }
        }

        float mnew  = fmaxf(m, lmax);
        float scale = __expf(m - mnew);
        l *= scale;
        #pragma unroll
        for (int d = 0; d < 8; d++) {
            accv[d].x *= scale; accv[d].y *= scale;
            accv[d].z *= scale; accv[d].w *= scale;
        }
        m = mnew;

        for (int c = 0; c < cnt; c++) {
            float p = __expf(sl[c] - m);
            l += p;
            const float4* vv4 = (const float4*)(vlb + (size_t)gl[c] * DHEAD);
            #pragma unroll
            for (int d = 0; d < 8; d++) {
                float4 vv = vv4[d];
                accv[d].x += p * vv.x; accv[d].y += p * vv.y;
                accv[d].z += p * vv.z; accv[d].w += p * vv.w;
            }
        }
    }

    const float inv = 1.0f / l;
    float* o = g_ctx + ((size_t)(bt * NTOK + n)) * D_MODEL + h * DHEAD;
    #pragma unroll
    for (int d = 0; d < 8; d++) {
        float4 r = make_float4(accv[d].x * inv, accv[d].y * inv,
                               accv[d].z * inv, accv[d].w * inv);
        ((float4*)o)[d] = r;
    }
}

// ---------------------------------------------------------------------------
// Kernel 4: output projection ctx @ Wo^T, scattered to (B, D, T, H, W)
// ---------------------------------------------------------------------------
__global__ __launch_bounds__(256) void out_kernel(const float* __restrict__ Wo,
                                                  float* __restrict__ out)
{
    __shared__ float As[8][128];
    __shared__ float Bs[8][128];

    const int tid = threadIdx.x;
    const int m0  = blockIdx.y * 128;
    const int c0  = blockIdx.x * 128;

    const int arow = tid >> 1;
    const int acol = (tid & 1) * 4;
    const int tx   = tid & 15;
    const int ty   = tid >> 4;

    float acc[8][8];
    #pragma unroll
    for (int i = 0; i < 8; i++)
        #pragma unroll
        for (int j = 0; j < 8; j++) acc[i][j] = 0.f;

    for (int k0 = 0; k0 < 256; k0 += 8) {
        float4 av = *(const float4*)(g_ctx + (size_t)(m0 + arow) * 256 + k0 + acol);
        float4 bv = *(const float4*)(Wo    + (size_t)(c0 + arow) * 256 + k0 + acol);
        As[acol + 0][arow] = av.x; As[acol + 1][arow] = av.y;
        As[acol + 2][arow] = av.z; As[acol + 3][arow] = av.w;
        Bs[acol + 0][arow] = bv.x; Bs[acol + 1][arow] = bv.y;
        Bs[acol + 2][arow] = bv.z; Bs[acol + 3][arow] = bv.w;
        __syncthreads();
        #pragma unroll
        for (int kk = 0; kk < 8; kk++) {
            float a[8], b[8];
            *(float4*)(a)     = *(const float4*)(&As[kk][ty * 8]);
            *(float4*)(a + 4) = *(const float4*)(&As[kk][ty * 8 + 4]);
            *(float4*)(b)     = *(const float4*)(&Bs[kk][tx * 8]);
            *(float4*)(b + 4) = *(const float4*)(&Bs[kk][tx * 8 + 4]);
            #pragma unroll
            for (int i = 0; i < 8; i++)
                #pragma unroll
                for (int j = 0; j < 8; j++)
                    acc[i][j] += a[i] * b[j];
        }
        __syncthreads();
    }

    // scatter: row m -> (b, t, n); col c -> channel d. out[b][c][t][n]
    const int bt_ = m0 >> 10;     // whole 128-row tile lies in one bt
    const int b   = bt_ >> 2;
    const int t   = bt_ & 3;
    const int n0  = (m0 & 1023) + ty * 8;

    #pragma unroll
    for (int j = 0; j < 8; j++) {
        int c = c0 + tx * 8 + j;
        float4 v0 = make_float4(acc[0][j], acc[1][j], acc[2][j], acc[3][j]);
        float4 v1 = make_float4(acc[4][j], acc[5][j], acc[6][j], acc[7][j]);
        float* p = out + ((size_t)(b * D_MODEL + c) * 4 + t) * 1024 + n0;
        *(float4*)(p)     = v0;
        *(float4*)(p + 4) = v1;
    }
}

// ---------------------------------------------------------------------------
extern "C" void kernel_launch(void* const* d_in, const int* in_sizes, int n_in,
                              void* d_out, int out_size)
{
    const float* x     = (const float*)d_in[0];
    const float* gamma = (const float*)d_in[1];
    const float* beta  = (const float*)d_in[2];
    const float* Wq    = (const float*)d_in[3];
    const float* Wk    = (const float*)d_in[4];
    const float* Wv    = (const float*)d_in[5];
    const float* Wkl   = (const float*)d_in[6];
    const float* Wvl   = (const float*)d_in[7];
    const float* Wo    = (const float*)d_in[8];
    const float* qb    = (const float*)d_in[9];
    float* out = (float*)d_out;

    ln_kernel<<<NROWS, 256>>>(x, gamma, beta);
    proj_kernel<<<dim3(2, 64, 5), 256>>>(Wq, Wk, Wv, Wkl, Wvl, qb);
    attn_kernel<<<dim3(8, 8, 8), 128>>>();
    out_kernel<<<dim3(2, 64), 256>>>(Wo, out);
}